// round 10
// baseline (speedup 1.0000x reference)
#include <cuda_runtime.h>

#define IN_DIM   8192
#define OUT_DIM  16384
#define TOP_K    327
#define NBINS    8193
#define NSLICE   16
#define SLICE    (OUT_DIM / NSLICE)   // 1024

// scratch (no allocations allowed)
__device__ int g_overlap[OUT_DIM];              // zeroed by k_out epilogue each launch
__device__ int g_hist[NBINS];                   // zeroed by k_gemv each launch
__device__ int g_chist[256];                    // 32-bin groups; zeroed by k_gemv
__device__ int g_slicehist[NSLICE][NBINS];      // plain-stored every launch (no zero needed)

// ---------------------------------------------------------------------------
// k_gemv: overlap[c] += sum over active rows of (p[row][c] > 0.5f)
//   grid = (16 col tiles, 64 row strips), 256 threads. Ballot-compacts its
//   own 128-row strip of x, streams active rows' float4 column slices.
//   ~5.9 TB/s — at the LTS ceiling. Also zeroes g_hist/g_chist (distributed).
// ---------------------------------------------------------------------------
#define GEMV_TB     256
#define STRIP       128
#define ROW_STRIPS  (IN_DIM / STRIP)        // 64
#define COLS_BLK    (GEMV_TB * 4)           // 1024
#define COL_TILES   (OUT_DIM / COLS_BLK)    // 16

__global__ __launch_bounds__(GEMV_TB, 7) void k_gemv(const int* __restrict__ x,
                                                     const float* __restrict__ p) {
    __shared__ int srows[STRIP];
    __shared__ int s_wcnt[4];

    const int t    = threadIdx.x;
    const int lane = t & 31;
    const int w    = t >> 5;
    const int r0   = blockIdx.y * STRIP;

    // distributed zero of the histogram scratch (1024 blocks x 8 bins)
    const int bid = blockIdx.y * COL_TILES + blockIdx.x;   // 0..1023
    if (t < 8)               g_hist[bid * 8 + t] = 0;
    if (bid == 0 && t == 8)  g_hist[8192] = 0;
    if (bid < 32 && t < 8)   g_chist[bid * 8 + t] = 0;

    // --- local compaction of this block's 128-row strip (warps 0-3) ---
    int a = 0, myrow = 0;
    unsigned m = 0;
    if (w < 4) {
        myrow = r0 + t;
        a = (x[myrow] != 0);
        m = __ballot_sync(0xffffffffu, a);
        if (lane == 0) s_wcnt[w] = __popc(m);
    }
    __syncthreads();
    const int nr = s_wcnt[0] + s_wcnt[1] + s_wcnt[2] + s_wcnt[3];
    if (w < 4 && a) {
        int off = 0;
        #pragma unroll
        for (int i = 0; i < 4; i++) if (i < w) off += s_wcnt[i];
        int rank = __popc(m & ((1u << lane) - 1u));
        srows[off + rank] = myrow;
    }
    __syncthreads();
    if (nr == 0) return;

    const int col4 = blockIdx.x * (COLS_BLK / 4) + t;
    const float4* __restrict__ p4 = (const float4*)p;
    const long stride4 = OUT_DIM / 4;

    int c0 = 0, c1 = 0, c2 = 0, c3 = 0;

    int r = 0;
    #pragma unroll 1
    for (; r + 4 <= nr; r += 4) {
        #pragma unroll
        for (int u = 0; u < 4; u++) {
            const int row = srows[r + u];
            const float4 v = __ldg(&p4[(long)row * stride4 + col4]);
            c0 += (v.x > 0.5f);
            c1 += (v.y > 0.5f);
            c2 += (v.z > 0.5f);
            c3 += (v.w > 0.5f);
        }
    }
    for (; r < nr; r++) {
        const int row = srows[r];
        const float4 v = __ldg(&p4[(long)row * stride4 + col4]);
        c0 += (v.x > 0.5f);
        c1 += (v.y > 0.5f);
        c2 += (v.z > 0.5f);
        c3 += (v.w > 0.5f);
    }

    const int cbase = col4 * 4;
    atomicAdd(&g_overlap[cbase + 0], c0);
    atomicAdd(&g_overlap[cbase + 1], c1);
    atomicAdd(&g_overlap[cbase + 2], c2);
    atomicAdd(&g_overlap[cbase + 3], c3);
}

// ---------------------------------------------------------------------------
// k_hist: grid 16 x 256. Block b histograms its 1024-value slice into smem,
// then merges: fine -> g_hist (atomic), 32-bin groups -> g_chist (atomic),
// full row -> g_slicehist[b] (plain store, fully overwritten each launch).
// ---------------------------------------------------------------------------
__global__ __launch_bounds__(256) void k_hist() {
    __shared__ int sh[NBINS];

    const int t   = threadIdx.x;
    const int blk = blockIdx.x;

    for (int i = t; i < NBINS; i += 256) sh[i] = 0;
    __syncthreads();

    // 4 values per thread (int4) from my slice
    const int4 v = ((const int4*)(g_overlap + blk * SLICE))[t];
    atomicAdd(&sh[v.x], 1);
    atomicAdd(&sh[v.y], 1);
    atomicAdd(&sh[v.z], 1);
    atomicAdd(&sh[v.w], 1);
    __syncthreads();

    // merge fine bins + store slice row
    for (int i = t; i < NBINS; i += 256) {
        int c = sh[i];
        g_slicehist[blk][i] = c;
        if (c) atomicAdd(&g_hist[i], c);
    }

    // coarse 32-bin groups: thread t covers bins [32t, 32t+32) (+bin 8192 on t=255)
    {
        int s = 0;
        const int base = t * 32;
        #pragma unroll
        for (int i = 0; i < 32; i++) s += sh[base + i];
        if (t == 255) s += sh[8192];
        if (s) atomicAdd(&g_chist[t], s);
    }
}

// ---------------------------------------------------------------------------
// k_out: grid 16 x 256. Every block redundantly finds T/rem from the coarse
// hist (1 int/thread + suffix scans; owner walks 32 fine bins of g_hist),
// computes its cross-slice tie offset from g_slicehist[*][T], then emits its
// own 1024-column slice (tie-break: lowest index wins) and zeroes it.
// ---------------------------------------------------------------------------
__global__ __launch_bounds__(256) void k_out(float* __restrict__ out) {
    __shared__ int s_w[8];
    __shared__ int s_wab[8];
    __shared__ int s_w2[8];
    __shared__ int s_T, s_rem, s_tieoff;

    const int t    = threadIdx.x;
    const int lane = t & 31;
    const int wid  = t >> 5;
    const int blk  = blockIdx.x;

    // ---- threshold selection from coarse hist ----
    const int loc = g_chist[t];   // count in my 32-bin group (t=255 incl. bin 8192)

    int suf = loc;                // suffix sum within warp (higher lane = higher bins)
    #pragma unroll
    for (int off = 1; off < 32; off <<= 1) {
        int v = __shfl_down_sync(0xffffffffu, suf, off);
        if (lane + off < 32) suf += v;
    }
    if (lane == 0) s_w[wid] = suf;
    __syncthreads();
    if (wid == 0) {
        int wv = (lane < 8) ? s_w[lane] : 0;
        int ws = wv;
        #pragma unroll
        for (int off = 1; off < 32; off <<= 1) {
            int v = __shfl_down_sync(0xffffffffu, ws, off);
            if (lane + off < 32) ws += v;
        }
        if (lane < 8) s_wab[lane] = ws - wv;   // warps strictly above mine
    }
    __syncthreads();

    const int above = s_wab[wid] + (suf - loc);
    if (above < TOP_K && above + loc >= TOP_K) {
        // owner: walk my 32(33) fine bins descending
        const int base = t * 32;
        const int n = (t == 255) ? 33 : 32;
        int a = above;
        for (int i = n - 1; i >= 0; i--) {
            int h = g_hist[base + i];
            if (a < TOP_K && a + h >= TOP_K) {
                s_T   = base + i;
                s_rem = TOP_K - a;
                break;
            }
            a += h;
        }
    }
    __syncthreads();
    const int T   = s_T;
    const int rem = s_rem;

    // ---- cross-slice tie offset: sum of ties at T in slices < blk ----
    if (wid == 0) {
        int tb = (lane < NSLICE) ? g_slicehist[lane][T] : 0;
        int acc = (lane < blk) ? tb : 0;
        #pragma unroll
        for (int o = 16; o; o >>= 1)
            acc += __shfl_xor_sync(0xffffffffu, acc, o);
        if (lane == 0) s_tieoff = acc;
    }
    __syncthreads();
    const int tieoff = s_tieoff;

    // ---- emit my slice ----
    int4* g4 = (int4*)(g_overlap + blk * SLICE);
    const int4 v = g4[t];
    int ov[4] = {v.x, v.y, v.z, v.w};

    int cnt = 0;
    #pragma unroll
    for (int j = 0; j < 4; j++) cnt += (ov[j] == T);

    int inc = cnt;  // warp inclusive scan of tie counts
    #pragma unroll
    for (int o = 1; o < 32; o <<= 1) {
        int n = __shfl_up_sync(0xffffffffu, inc, o);
        if (lane >= o) inc += n;
    }
    if (lane == 31) s_w2[wid] = inc;
    __syncthreads();
    if (wid == 0) {
        int tot = (lane < 8) ? s_w2[lane] : 0;
        int sv = tot;
        #pragma unroll
        for (int o = 1; o < 32; o <<= 1) {
            int n = __shfl_up_sync(0xffffffffu, sv, o);
            if (lane >= o) sv += n;
        }
        if (lane < 8) s_w2[lane] = sv - tot;   // exclusive warp offsets
    }
    __syncthreads();
    int run = tieoff + s_w2[wid] + (inc - cnt);

    float r[4];
    #pragma unroll
    for (int j = 0; j < 4; j++) {
        int vv = ov[j];
        float o;
        if (vv > T) {
            o = 1.0f;
        } else if (vv == T) {
            o = (run < rem) ? 1.0f : 0.0f;
            run++;
        } else {
            o = 0.0f;
        }
        r[j] = o;
    }
    ((float4*)(out + blk * SLICE))[t] = make_float4(r[0], r[1], r[2], r[3]);

    // reset my slice for the next graph replay
    g4[t] = make_int4(0, 0, 0, 0);
}

// ---------------------------------------------------------------------------
extern "C" void kernel_launch(void* const* d_in, const int* in_sizes, int n_in,
                              void* d_out, int out_size) {
    const int*   x = (const int*)d_in[0];   // [1, 8192] int32
    const float* p = (const float*)d_in[1]; // [8192, 16384] float32
    float* out = (float*)d_out;             // [1, 16384] float32

    dim3 grid(COL_TILES, ROW_STRIPS);
    k_gemv<<<grid, GEMV_TB>>>(x, p);
    k_hist<<<NSLICE, 256>>>();
    k_out<<<NSLICE, 256>>>(out);
}